// round 6
// baseline (speedup 1.0000x reference)
#include <cuda_runtime.h>
#include <math.h>

// Problem constants
#define DD    1024
#define KCLS  5
#define NSUP  5      // support per class
#define NQRY  75     // total queries (K*Q)
#define NAUG  40
#define NROWS 100    // 25 support + 75 queries
#define NSEG  8      // per-class dim segments (8*128 = 1024)
#define NBLK  120    // persistent grid (<=148 -> guaranteed co-resident)
#define NTHR  512
// hyperbolic constants: c = 0.01, sqrt(c) = 0.1

// ---------------- device scratch (static, no runtime alloc) ----------------
__device__ double g_P[NROWS * DD];      // projected Poincare points
__device__ double g_X2[NROWS];          // ||x||^2 per point
__device__ double g_KFAC[NROWS];        // 2/(1 + c||x||^2)
__device__ double g_LAM[NROWS];         // Lorentz factor of Klein point
__device__ double g_PROTO[KCLS * DD];   // initial prototypes
__device__ double g_PX2[KCLS];
__device__ int    g_PRED[NQRY];
__device__ double g_NLL[NQRY];
__device__ double g_MKD[KCLS * DD];     // masked Klein mean per dim
__device__ double g_STD[KCLS * DD];     // per-dim std of masked Euclid pts
__device__ double g_MK2P[KCLS * NSEG];  // partial sums of mkd^2
__device__ double g_CA[KCLS * NAUG];
__device__ double g_CB[KCLS * NAUG];
__device__ double g_WL2[KCLS * NAUG];
__device__ double g_M2[KCLS * DD];      // unnormalized refined Klein mean
__device__ double g_MK2BP[KCLS * NSEG];

// software grid barrier state
__device__ int          g_count;        // zero-initialized; restored to 0 each use
__device__ volatile int g_gen;          // generation counter (monotonic, wrap-safe)

// ---------------- helpers ----------------
__device__ __forceinline__ void grid_barrier() {
    __syncthreads();                         // all block writes ordered before thread0
    if (threadIdx.x == 0) {
        int gen = g_gen;
        __threadfence();                     // release: make block's writes GPU-visible
        if (atomicAdd(&g_count, 1) == NBLK - 1) {
            g_count = 0;
            __threadfence();
            g_gen = gen + 1;                 // release the others
        } else {
            while (g_gen == gen) __nanosleep(32);
            __threadfence();                 // acquire
        }
    }
    __syncthreads();
}

__device__ __forceinline__ double blk_reduce16(double v, double* sbuf) {
    #pragma unroll
    for (int o = 16; o > 0; o >>= 1) v += __shfl_down_sync(0xffffffffu, v, o);
    int w = threadIdx.x >> 5, l = threadIdx.x & 31;
    if (l == 0) sbuf[w] = v;
    __syncthreads();
    if (w == 0) {
        double r = (l < 16) ? sbuf[l] : 0.0;
        #pragma unroll
        for (int o = 16; o > 0; o >>= 1) r += __shfl_down_sync(0xffffffffu, r, o);
        if (l == 0) sbuf[0] = r;
    }
    __syncthreads();
    double r = sbuf[0];
    __syncthreads();
    return r;
}

// Poincare distance given ||x||^2, ||y||^2, <x,y>  (c = 0.01)
__device__ __forceinline__ double hdist(double x2, double y2, double xy) {
    double a    = 1.0 - 0.02 * xy + 0.01 * y2;
    double b    = 1.0 - 0.01 * x2;
    double num2 = a * a * x2 + b * b * y2 - 2.0 * a * b * xy;
    double den  = fmax(1.0 - 0.02 * xy + 1e-4 * x2 * y2, 1e-5);
    double nrm  = sqrt(fmax(num2, 0.0)) / den;
    double z    = fmin(fmax(0.1 * nrm, -1.0 + 1e-5), 1.0 - 1e-5);
    return 20.0 * atanh(z);
}

// ---------------- fused persistent kernel: all 7 stages ----------------
__global__ void __launch_bounds__(NTHR) k_fused(const float* __restrict__ feat,
                                                const int*   __restrict__ label,
                                                const float* __restrict__ noise,
                                                float*       __restrict__ out) {
    __shared__ double sbuf[16];
    __shared__ double sred[16 * KCLS];
    __shared__ double sdots[KCLS];
    __shared__ double sden2[KCLS], sy2[KCLS];
    // stage B
    __shared__ double sB_co[NSUP];
    __shared__ double sB_rw;
    // stage D
    __shared__ double sD_me[80], sD_lam[80], sD_coef[80];
    __shared__ int    sD_row[80];
    __shared__ double sD_ak[4][128], sD_ae[4][128], sD_ae2[4][128];
    __shared__ double sD_m2[128];
    __shared__ double sD_rw, sD_cnt;
    __shared__ int    sD_m;
    // stage E
    __shared__ double sE_red[16 * 2];
    __shared__ double sE_rden, sE_x2sp, sE_ptfac;
    // stage F
    __shared__ double sF_cb[NAUG], sF_co[NSUP];
    __shared__ double sF_accN[4][128], sF_m2[128];
    __shared__ double sF_rw2, sF_SA, sF_ptfac, sF_rden;

    int b   = blockIdx.x;
    int tid = threadIdx.x;
    int w   = tid >> 5, l = tid & 31;

    // ===== Stage A: expmap0 + project + Klein scalars (100 rows) =====
    if (b < NROWS) {
        const float* u = feat + (size_t)b * DD;
        double uv0 = (double)u[tid], uv1 = (double)u[tid + 512];
        double s2 = blk_reduce16(uv0 * uv0 + uv1 * uv1, sbuf);

        double nrmu = sqrt(s2);
        double un   = fmax(nrmu, 1e-5);
        double s1   = tanh(0.1 * un) / (0.1 * un);
        double e0n  = s1 * nrmu;
        double nrm  = fmax(e0n, 1e-5);
        double s    = s1;
        if (nrm > 9.99) s = s1 * (9.99 / nrm);
        double x2 = s * s * s2;

        g_P[(size_t)b * DD + tid]       = s * uv0;
        g_P[(size_t)b * DD + tid + 512] = s * uv1;

        if (tid == 0) {
            g_X2[b] = x2;
            double kf = 2.0 / (1.0 + 0.01 * x2);
            double k2 = kf * kf * x2;
            g_KFAC[b] = kf;
            g_LAM[b]  = 1.0 / sqrt(fmax(1.0 - 0.01 * k2, 1e-5));
        }
    }
    grid_barrier();

    // ===== Stage B: initial prototypes (5 classes) =====
    if (b < KCLS) {
        int c = b;
        if (tid < NSUP) sB_co[tid] = g_LAM[c * NSUP + tid] * g_KFAC[c * NSUP + tid];
        if (tid == 0) {
            double ws = 0.0;
            for (int n = 0; n < NSUP; n++) ws += g_LAM[c * NSUP + n];
            sB_rw = 1.0 / ws;
        }
        __syncthreads();
        double rwsum = sB_rw;

        double a0 = 0.0, a1 = 0.0;
        #pragma unroll
        for (int n = 0; n < NSUP; n++) {
            a0 += sB_co[n] * g_P[(size_t)(c * NSUP + n) * DD + tid];
            a1 += sB_co[n] * g_P[(size_t)(c * NSUP + n) * DD + tid + 512];
        }
        double mk0 = a0 * rwsum, mk1 = a1 * rwsum;
        double mk2 = blk_reduce16(mk0 * mk0 + mk1 * mk1, sbuf);
        double den = 1.0 + sqrt(fmax(1.0 - 0.01 * mk2, 0.0));
        double rden = 1.0 / den;
        g_PROTO[(size_t)c * DD + tid]       = mk0 * rden;
        g_PROTO[(size_t)c * DD + tid + 512] = mk1 * rden;
        if (tid == 0) g_PX2[c] = mk2 / (den * den);
    }
    grid_barrier();

    // ===== Stage C: dist matrix, argmax pred, per-query NLL (75 queries) =====
    if (b < NQRY) {
        int row = 25 + b;
        double x0 = g_P[(size_t)row * DD + tid];
        double x1 = g_P[(size_t)row * DD + tid + 512];
        double p5[KCLS];
        #pragma unroll
        for (int j = 0; j < KCLS; j++)
            p5[j] = x0 * g_PROTO[(size_t)j * DD + tid] + x1 * g_PROTO[(size_t)j * DD + tid + 512];
        #pragma unroll
        for (int j = 0; j < KCLS; j++) {
            double v = p5[j];
            #pragma unroll
            for (int o = 16; o > 0; o >>= 1) v += __shfl_down_sync(0xffffffffu, v, o);
            if (l == 0) sred[w * KCLS + j] = v;
        }
        __syncthreads();
        if (tid < KCLS) {
            double r = 0.0;
            #pragma unroll
            for (int ww = 0; ww < 16; ww++) r += sred[ww * KCLS + tid];
            sdots[tid] = r;
        }
        __syncthreads();
        if (tid == 0) {
            double x2 = g_X2[row];
            double dist[KCLS];
            int best = 0; double bd = 1e300;
            #pragma unroll
            for (int j = 0; j < KCLS; j++) {
                dist[j] = hdist(x2, g_PX2[j], sdots[j]);
                if (dist[j] < bd) { bd = dist[j]; best = j; }
            }
            g_PRED[b] = best;
            double m = -1e300;
            #pragma unroll
            for (int j = 0; j < KCLS; j++) m = fmax(m, -dist[j]);
            double se = 0.0;
            #pragma unroll
            for (int j = 0; j < KCLS; j++) se += exp(-dist[j] - m);
            double lse = m + log(se);
            int lbl = label[NQRY + b];
            g_NLL[b] = lse + dist[lbl];   // log_softmax(log_softmax(x)) == log_softmax(x)
        }
    }
    grid_barrier();

    // ===== Stage D: per-class per-dim masked Klein mean + Euclid std (40 blocks) =====
    if (b < KCLS * NSEG) {
        int c = b >> 3, s = b & 7;
        int g    = tid >> 7;
        int lane = tid & 127;
        int d    = s * 128 + lane;

        if (tid < 80) {
            int row; double mm;
            if (tid < NSUP) { row = c * NSUP + tid; mm = 1.0; }
            else            { row = 25 + (tid - NSUP); mm = (g_PRED[tid - NSUP] == c) ? 1.0 : 0.0; }
            sD_me[tid]   = mm;
            sD_row[tid]  = row;
            double lm    = g_LAM[row];
            sD_lam[tid]  = lm;
            sD_coef[tid] = lm * g_KFAC[row];
        }
        __syncthreads();
        if (tid == 0) {
            double wsum = 0.0, cn = 0.0; int m = 0;
            for (int p = 0; p < 80; p++) {
                if (sD_me[p] != 0.0) {
                    wsum += sD_lam[p]; cn += 1.0;
                    sD_row[m] = sD_row[p]; sD_coef[m] = sD_coef[p]; m++;
                }
            }
            sD_rw = 1.0 / wsum; sD_cnt = cn; sD_m = m;
        }
        __syncthreads();
        int m = sD_m;

        double ak = 0.0, ae = 0.0, ae2 = 0.0;
        #pragma unroll 4
        for (int ji = g; ji < m; ji += 4) {
            int row   = sD_row[ji];
            double Pv = g_P[(size_t)row * DD + d];
            double Ev = (double)feat[(size_t)row * DD + d];
            ak  = fma(sD_coef[ji], Pv, ak);
            ae  += Ev;
            ae2 = fma(Ev, Ev, ae2);
        }
        sD_ak[g][lane] = ak; sD_ae[g][lane] = ae; sD_ae2[g][lane] = ae2;
        __syncthreads();

        if (g == 0) {
            double AK  = sD_ak[0][lane]  + sD_ak[1][lane]  + sD_ak[2][lane]  + sD_ak[3][lane];
            double AE  = sD_ae[0][lane]  + sD_ae[1][lane]  + sD_ae[2][lane]  + sD_ae[3][lane];
            double AE2 = sD_ae2[0][lane] + sD_ae2[1][lane] + sD_ae2[2][lane] + sD_ae2[3][lane];
            double cnt = sD_cnt;
            double mkd = AK * sD_rw;
            g_MKD[(size_t)c * DD + d] = mkd;
            double var = fmax(AE2 - AE * AE / cnt, 0.0) / (cnt - 1.0);
            g_STD[(size_t)c * DD + d] = sqrt(var);
            sD_m2[lane] = mkd * mkd;
        }
        __syncthreads();
        if (tid == 0) {
            double part = 0.0;
            for (int i = 0; i < 128; i++) part += sD_m2[i];
            g_MK2P[c * NSEG + s] = part;
        }
    }
    grid_barrier();

    // ===== Stage E: per (class, aug-row) reductions + scalar chain (200 rows over 120 blocks) =====
    for (int r = b; r < KCLS * NAUG; r += NBLK) {
        int c = r / NAUG, j = r % NAUG;
        if (tid == 0) {
            double mk2 = 0.0;
            for (int s = 0; s < NSEG; s++) mk2 += g_MK2P[c * NSEG + s];
            double den = 1.0 + sqrt(fmax(1.0 - 0.01 * mk2, 0.0));
            sE_rden  = 1.0 / den;
            double x2sp = mk2 / (den * den);
            sE_x2sp  = x2sp;
            sE_ptfac = 1.0 - 0.01 * x2sp;
        }
        __syncthreads();
        double rden = sE_rden, x2sp = sE_x2sp, ptfac = sE_ptfac;

        const float* nz = noise + (size_t)r * DD;
        double a2 = 0.0, ad = 0.0;
        {
            double wv0 = (double)nz[tid] * g_STD[(size_t)c * DD + tid];
            double wv1 = (double)nz[tid + 512] * g_STD[(size_t)c * DD + tid + 512];
            a2 = fma(wv0, wv0, fma(wv1, wv1, 0.0));
            ad = fma(g_MKD[(size_t)c * DD + tid], wv0,
                 fma(g_MKD[(size_t)c * DD + tid + 512], wv1, 0.0));
        }
        #pragma unroll
        for (int o = 16; o > 0; o >>= 1) {
            a2 += __shfl_down_sync(0xffffffffu, a2, o);
            ad += __shfl_down_sync(0xffffffffu, ad, o);
        }
        if (l == 0) { sE_red[w * 2] = a2; sE_red[w * 2 + 1] = ad; }
        __syncthreads();

        if (tid == 0) {
            double A2 = 0.0, AD = 0.0;
            #pragma unroll
            for (int ww = 0; ww < 16; ww++) { A2 += sE_red[ww * 2]; AD += sE_red[ww * 2 + 1]; }
            double pt2 = ptfac * ptfac * A2;
            double dxp = ptfac * rden * AD;

            double lamx = 2.0 / fmax(1.0 - 0.01 * x2sp, 1e-5);
            double un  = fmax(sqrt(pt2), 1e-5);
            double t   = tanh(0.05 * lamx * un) / (0.1 * un);
            double y2  = t * t * pt2;
            double xy  = t * dxp;
            double A   = 1.0 + 0.02 * xy + 0.01 * y2;
            double B   = ptfac * t;
            double dn  = fmax(1.0 + 0.02 * xy + 1e-4 * x2sp * y2, 1e-5);
            double ex2 = (A * A * x2sp + B * B * pt2 + 2.0 * A * B * dxp) / (dn * dn);
            double kf  = 2.0 / (1.0 + 0.01 * ex2);
            double k2  = kf * kf * ex2;
            double lm  = 1.0 / sqrt(fmax(1.0 - 0.01 * k2, 1e-5));
            g_CA[r]  = lm * kf * A / dn;
            g_CB[r]  = lm * kf * B / dn;
            g_WL2[r] = lm;
        }
        __syncthreads();
    }
    grid_barrier();

    // ===== Stage F: refined prototype per dim (40 blocks) =====
    if (b < KCLS * NSEG) {
        int c = b >> 3, s = b & 7;
        int g    = tid >> 7;
        int lane = tid & 127;
        int d    = s * 128 + lane;

        if (tid < NAUG) sF_cb[tid] = g_CB[c * NAUG + tid];
        if (tid >= 64 && tid < 64 + NSUP)
            sF_co[tid - 64] = g_LAM[c * NSUP + tid - 64] * g_KFAC[c * NSUP + tid - 64];
        if (tid == 0) {
            double mk2 = 0.0;
            for (int t = 0; t < NSEG; t++) mk2 += g_MK2P[c * NSEG + t];
            double den = 1.0 + sqrt(fmax(1.0 - 0.01 * mk2, 0.0));
            double x2sp = mk2 / (den * den);
            sF_rden  = 1.0 / den;
            sF_ptfac = 1.0 - 0.01 * x2sp;
            double w2 = 0.0, sa = 0.0;
            for (int n = 0; n < NSUP; n++) w2 += g_LAM[c * NSUP + n];
            for (int j = 0; j < NAUG; j++) { w2 += g_WL2[c * NAUG + j]; sa += g_CA[c * NAUG + j]; }
            sF_rw2 = 1.0 / w2; sF_SA = sa;
        }
        __syncthreads();

        double accN = 0.0;
        #pragma unroll
        for (int ji = 0; ji < 10; ji++) {
            int j = g * 10 + ji;
            accN = fma(sF_cb[j], (double)noise[((size_t)(c * NAUG + j)) * DD + d], accN);
        }
        sF_accN[g][lane] = accN;
        __syncthreads();

        if (g == 0) {
            double acc = 0.0;
            #pragma unroll
            for (int n = 0; n < NSUP; n++)
                acc = fma(sF_co[n], g_P[(size_t)(c * NSUP + n) * DD + d], acc);
            double spd = g_MKD[(size_t)c * DD + d] * sF_rden;
            acc += sF_SA * spd;
            double AN = sF_accN[0][lane] + sF_accN[1][lane] + sF_accN[2][lane] + sF_accN[3][lane];
            acc += AN * sF_ptfac * g_STD[(size_t)c * DD + d];

            double m2 = acc * sF_rw2;
            g_M2[(size_t)c * DD + d] = m2;
            sF_m2[lane] = m2 * m2;
        }
        __syncthreads();
        if (tid == 0) {
            double part = 0.0;
            for (int i = 0; i < 128; i++) part += sF_m2[i];
            g_MK2BP[c * NSEG + s] = part;
        }
    }
    grid_barrier();

    // ===== Stage G: dist_new -> softmax y_pred; loss =====
    if (b < NQRY) {
        if (tid < KCLS) {
            double mk2b = 0.0;
            for (int s = 0; s < NSEG; s++) mk2b += g_MK2BP[tid * NSEG + s];
            double den2 = 1.0 + sqrt(fmax(1.0 - 0.01 * mk2b, 0.0));
            sden2[tid] = den2;
            sy2[tid]   = mk2b / (den2 * den2);
        }

        int row = 25 + b;
        double x0 = g_P[(size_t)row * DD + tid];
        double x1 = g_P[(size_t)row * DD + tid + 512];
        double p5[KCLS];
        #pragma unroll
        for (int j = 0; j < KCLS; j++)
            p5[j] = x0 * g_M2[(size_t)j * DD + tid] + x1 * g_M2[(size_t)j * DD + tid + 512];
        #pragma unroll
        for (int j = 0; j < KCLS; j++) {
            double v = p5[j];
            #pragma unroll
            for (int o = 16; o > 0; o >>= 1) v += __shfl_down_sync(0xffffffffu, v, o);
            if (l == 0) sred[w * KCLS + j] = v;
        }
        __syncthreads();
        if (tid < KCLS) {
            double r = 0.0;
            #pragma unroll
            for (int ww = 0; ww < 16; ww++) r += sred[ww * KCLS + tid];
            sdots[tid] = r;
        }
        __syncthreads();

        if (tid == 0) {
            double x2 = g_X2[row];
            double dist[KCLS];
            double m = -1e300;
            #pragma unroll
            for (int j = 0; j < KCLS; j++) {
                dist[j] = hdist(x2, sy2[j], sdots[j] / sden2[j]);
                m = fmax(m, -dist[j]);
            }
            double e[KCLS]; double se = 0.0;
            #pragma unroll
            for (int j = 0; j < KCLS; j++) { e[j] = exp(-dist[j] - m); se += e[j]; }
            #pragma unroll
            for (int j = 0; j < KCLS; j++) out[b * KCLS + j] = (float)(e[j] / se);
        }
    } else if (b == NQRY) {
        if (tid == 0) {
            double ssum = 0.0;
            for (int i = 0; i < NQRY; i++) ssum += g_NLL[i];
            out[NQRY * KCLS] = (float)(ssum / (double)NQRY);
        }
    }
}

// ---------------- launch ----------------
extern "C" void kernel_launch(void* const* d_in, const int* in_sizes, int n_in,
                              void* d_out, int out_size) {
    const float* feat  = (const float*)d_in[0];
    const int*   label = (const int*)  d_in[1];
    const float* noise = (const float*)d_in[2];
    float* out = (float*)d_out;

    k_fused<<<NBLK, NTHR>>>(feat, label, noise, out);
}